// round 11
// baseline (speedup 1.0000x reference)
#include <cuda_runtime.h>
#include <cstdint>

#define NN 100000
#define EE 1600000
#define D  64
#define MAXDEG 64    // avg degree = 16; P(deg > 64) ~ e^-126, plus runtime clamp
#define NBANDS 6250  // 100000 / 16, exact
#define FGRID 296    // 2 CTAs/SM * 148 SMs
#define W1S 18       // uint2 stride for 16-entry W-half rows (bank-conflict-free)

// Scratch (device globals: allocation-free per harness rules)
__device__ int   g_cnt[NN];
__device__ int   g_csr[(size_t)NN * MAXDEG];
__device__ float g_agg[(size_t)NN * D];
__device__ float g_y1[(size_t)NN * D];     // x @ W1^T partial product
// W pre-packed bf16 fragments: index ((n*8 + chunk)*4 + t4) -> uint2 {b0, b1}
__device__ uint2 g_bhi[64 * 8 * 4];
__device__ uint2 g_blo[64 * 8 * 4];

// ---------------------------------------------------------------------------
// bf16 helpers (plain sm_80+ PTX)
// ---------------------------------------------------------------------------
__device__ __forceinline__ uint32_t pack_bf16(float lo, float hi) {
    uint32_t r;  // first asm source lands in the UPPER half
    asm("cvt.rn.bf16x2.f32 %0, %1, %2;" : "=r"(r) : "f"(hi), "f"(lo));
    return r;
}
__device__ __forceinline__ void split2_bf16(float f0, float f1,
                                            uint32_t& hi, uint32_t& lo) {
    hi = pack_bf16(f0, f1);
    float h0 = __uint_as_float(hi << 16);
    float h1 = __uint_as_float(hi & 0xffff0000u);
    lo = pack_bf16(f0 - h0, f1 - h1);
}
__device__ __forceinline__ void mma_bf16(float* c, uint32_t a0, uint32_t a1,
                                         uint32_t a2, uint32_t a3,
                                         uint32_t b0, uint32_t b1) {
    asm volatile(
        "mma.sync.aligned.m16n8k16.row.col.f32.bf16.bf16.f32 "
        "{%0,%1,%2,%3}, {%4,%5,%6,%7}, {%8,%9}, {%0,%1,%2,%3};"
        : "+f"(c[0]), "+f"(c[1]), "+f"(c[2]), "+f"(c[3])
        : "r"(a0), "r"(a1), "r"(a2), "r"(a3), "r"(b0), "r"(b1));
}

// ---------------------------------------------------------------------------
// Kernel 1: setup = zero counters + pack W fragments (both k-halves)
// ---------------------------------------------------------------------------
__global__ void setup_kernel(const float* __restrict__ W) {
    int i = blockIdx.x * blockDim.x + threadIdx.x;
    if (i < NN) g_cnt[i] = 0;
    if (i < 64 * 8 * 4) {
        int t4 = i & 3;
        int c  = (i >> 2) & 7;
        int n  = i >> 5;
        const float* wr = W + n * 128 + c * 16;
        uint32_t h0, l0, h1, l1;
        split2_bf16(wr[2 * t4],     wr[2 * t4 + 1],     h0, l0);
        split2_bf16(wr[8 + 2 * t4], wr[8 + 2 * t4 + 1], h1, l1);
        g_bhi[i] = make_uint2(h0, h1);
        g_blo[i] = make_uint2(l0, l1);
    }
}

// smem for kernel 2 (uint32 units): W1 fragments only
#define SM2_WHI   0
#define SM2_WLO   (64 * W1S * 2)
#define SM2_TOTAL (2 * 64 * W1S * 2)    // 4608 u32 = 18 KB

// ---------------------------------------------------------------------------
// Kernel 2: BLOCK-SPECIALIZED  y1-GEMM (blocks < FGRID)  ||  CSR fill (rest).
// y1 = x @ W1^T via bf16 3-way-split MMA (persistent, 16-node bands).
// Fill: 2 edges per thread, int atomic cursor into padded CSR.
// The two roles touch different pipes (tensor/LDG vs atomics/L2-writes)
// and run concurrently within one launch.
// ---------------------------------------------------------------------------
__global__ void __launch_bounds__(256, 2)
fill_y1_kernel(const float* __restrict__ x,
               const int* __restrict__ ei) {
    if (blockIdx.x < FGRID) {
        // ---------------- y1-GEMM role ----------------
        extern __shared__ uint32_t su[];
        uint2* whi = (uint2*)(su + SM2_WHI);    // [64][W1S]
        uint2* wlo = (uint2*)(su + SM2_WLO);
        const int tid  = threadIdx.x;
        const int wid  = tid >> 5;
        const int lane = tid & 31;

        for (int t = tid; t < 64 * 16; t += 256) {
            int n = t >> 4;
            int s = t & 15;                    // chunks 0-3 of g_b*
            whi[n * W1S + s] = g_bhi[n * 32 + s];
            wlo[n * W1S + s] = g_blo[n * 32 + s];
        }
        __syncthreads();

        const int g  = lane >> 2;
        const int t4 = lane & 3;
        const int gwarp  = blockIdx.x * 8 + wid;
        const int nwarps = FGRID * 8;

        for (int band = gwarp; band < NBANDS; band += nwarps) {
            const int node0 = band * 16 + g;
            const float* xr0 = x + (size_t)node0 * D;
            const float* xr1 = x + (size_t)(node0 + 8) * D;

            float acc[32];
#pragma unroll
            for (int i = 0; i < 32; i++) acc[i] = 0.0f;

#pragma unroll
            for (int c = 0; c < 4; c++) {
                int kb = c * 16;
                float2 f00 = *(const float2*)(xr0 + kb + 2 * t4);
                float2 f01 = *(const float2*)(xr0 + kb + 8 + 2 * t4);
                float2 f10 = *(const float2*)(xr1 + kb + 2 * t4);
                float2 f11 = *(const float2*)(xr1 + kb + 8 + 2 * t4);

                uint32_t ah0, al0, ah1, al1, ah2, al2, ah3, al3;
                split2_bf16(f00.x, f00.y, ah0, al0);
                split2_bf16(f10.x, f10.y, ah1, al1);
                split2_bf16(f01.x, f01.y, ah2, al2);
                split2_bf16(f11.x, f11.y, ah3, al3);

#pragma unroll
                for (int nt = 0; nt < 8; nt++) {
                    int off = (nt * 8 + g) * W1S + c * 4 + t4;
                    uint2 bh = whi[off];
                    uint2 bl = wlo[off];
                    float* cc = acc + nt * 4;
                    mma_bf16(cc, ah0, ah1, ah2, ah3, bh.x, bh.y);
                    mma_bf16(cc, ah0, ah1, ah2, ah3, bl.x, bl.y);
                    mma_bf16(cc, al0, al1, al2, al3, bh.x, bh.y);
                }
            }

            float* y0p = g_y1 + (size_t)node0 * D;
            float* y1p = g_y1 + (size_t)(node0 + 8) * D;
#pragma unroll
            for (int nt = 0; nt < 8; nt++) {
                int col = nt * 8 + 2 * t4;
                *(float2*)(y0p + col) = make_float2(acc[nt * 4 + 0], acc[nt * 4 + 1]);
                *(float2*)(y1p + col) = make_float2(acc[nt * 4 + 2], acc[nt * 4 + 3]);
            }
        }
    } else {
        // ---------------- fill role ----------------
        int t = (blockIdx.x - FGRID) * 256 + threadIdx.x;
        if (t * 2 >= EE) return;
        int2 d2 = *(const int2*)(ei + 2 * t);
        int2 s2 = *(const int2*)(ei + EE + 2 * t);
        int p0 = atomicAdd(g_cnt + d2.x, 1);
        if (p0 < MAXDEG) g_csr[(size_t)d2.x * MAXDEG + p0] = s2.x;
        int p1 = atomicAdd(g_cnt + d2.y, 1);
        if (p1 < MAXDEG) g_csr[(size_t)d2.y * MAXDEG + p1] = s2.y;
    }
}

// ---------------------------------------------------------------------------
// Kernel 3: fp32 mean aggregation (R8 form — known good, rel_err 5.5e-6).
// 2 nodes per warp: 16 lanes x float4 per 256B row; one LDG.128 warp instr
// fetches neighbor rows of both nodes. L2-resident x.
// ---------------------------------------------------------------------------
__global__ void __launch_bounds__(256)
aggregate_kernel(const float* __restrict__ x) {
    int warp = (blockIdx.x * blockDim.x + threadIdx.x) >> 5;
    int lane = threadIdx.x & 31;
    if (warp * 2 >= NN) return;
    const int node  = warp * 2 + (lane >> 4);
    const int lane16 = lane & 15;

    int cnt = g_cnt[node];
    int nloc = min(cnt, MAXDEG);
    int nmax = max(nloc, __shfl_xor_sync(0xffffffffu, nloc, 16));

    const int4* csr4 = (const int4*)(g_csr + (size_t)node * MAXDEG);
    const float4* x4 = (const float4*)x;

    float4 acc = make_float4(0.f, 0.f, 0.f, 0.f);
    for (int i = 0; i < nmax; i += 8) {
        int4 a = csr4[(i >> 2)];
        int4 c = csr4[(i >> 2) + 1];
        float4 v;
        if (i + 0 < nloc) { v = x4[(size_t)a.x * 16 + lane16]; acc.x += v.x; acc.y += v.y; acc.z += v.z; acc.w += v.w; }
        if (i + 1 < nloc) { v = x4[(size_t)a.y * 16 + lane16]; acc.x += v.x; acc.y += v.y; acc.z += v.z; acc.w += v.w; }
        if (i + 2 < nloc) { v = x4[(size_t)a.z * 16 + lane16]; acc.x += v.x; acc.y += v.y; acc.z += v.z; acc.w += v.w; }
        if (i + 3 < nloc) { v = x4[(size_t)a.w * 16 + lane16]; acc.x += v.x; acc.y += v.y; acc.z += v.z; acc.w += v.w; }
        if (i + 4 < nloc) { v = x4[(size_t)c.x * 16 + lane16]; acc.x += v.x; acc.y += v.y; acc.z += v.z; acc.w += v.w; }
        if (i + 5 < nloc) { v = x4[(size_t)c.y * 16 + lane16]; acc.x += v.x; acc.y += v.y; acc.z += v.z; acc.w += v.w; }
        if (i + 6 < nloc) { v = x4[(size_t)c.z * 16 + lane16]; acc.x += v.x; acc.y += v.y; acc.z += v.z; acc.w += v.w; }
        if (i + 7 < nloc) { v = x4[(size_t)c.w * 16 + lane16]; acc.x += v.x; acc.y += v.y; acc.z += v.z; acc.w += v.w; }
    }

    float inv = 1.0f / fmaxf((float)cnt, 1.0f);
    acc.x *= inv; acc.y *= inv; acc.z *= inv; acc.w *= inv;
    ((float4*)g_agg)[(size_t)node * 16 + lane16] = acc;
}

// smem for kernel 4 (uint32 units): W2 fragments + bias/gamma/beta
#define SMF_WHI   0
#define SMF_WLO   (64 * W1S * 2)
#define SMF_BIAS  (2 * 64 * W1S * 2)
#define SMF_GAM   (SMF_BIAS + 64)
#define SMF_BET   (SMF_BIAS + 128)
#define SMF_TOTAL (SMF_BIAS + 192)      // 4800 u32 = 19.2 KB

// ---------------------------------------------------------------------------
// Kernel 4: finalize2 — agg-half MMA (96/band), accumulators initialized
// from y1, then bias + ReLU + LayerNorm + store.
// ---------------------------------------------------------------------------
__global__ void __launch_bounds__(256, 2)
finalize2_kernel(const float* __restrict__ b,
                 const float* __restrict__ gamma,
                 const float* __restrict__ beta,
                 float* __restrict__ out) {
    extern __shared__ uint32_t su[];
    uint2* whi = (uint2*)(su + SMF_WHI);    // [64][W1S], chunks 4-7 of W
    uint2* wlo = (uint2*)(su + SMF_WLO);
    float* bias = (float*)(su + SMF_BIAS);
    float* gam  = (float*)(su + SMF_GAM);
    float* bet  = (float*)(su + SMF_BET);

    const int tid  = threadIdx.x;
    const int wid  = tid >> 5;
    const int lane = tid & 31;

    for (int t = tid; t < 64 * 16; t += 256) {
        int n = t >> 4;
        int s = t & 15;                    // chunks 4-7 = entries 16..31
        whi[n * W1S + s] = g_bhi[n * 32 + 16 + s];
        wlo[n * W1S + s] = g_blo[n * 32 + 16 + s];
    }
    if (tid < 64) {
        bias[tid] = b[tid];
        gam[tid]  = gamma[tid];
        bet[tid]  = beta[tid];
    }
    __syncthreads();

    const int g  = lane >> 2;
    const int t4 = lane & 3;
    const int gwarp  = blockIdx.x * 8 + wid;
    const int nwarps = FGRID * 8;

    for (int band = gwarp; band < NBANDS; band += nwarps) {
        const int node0 = band * 16 + g;
        const float* ar0 = g_agg + (size_t)node0 * D;
        const float* ar1 = g_agg + (size_t)(node0 + 8) * D;
        const float* y0p = g_y1 + (size_t)node0 * D;
        const float* y1p = g_y1 + (size_t)(node0 + 8) * D;

        // init accumulators from y1 (x @ W1^T) — high-MLP batched loads
        float acc[32];
#pragma unroll
        for (int nt = 0; nt < 8; nt++) {
            int col = nt * 8 + 2 * t4;
            float2 a = *(const float2*)(y0p + col);
            float2 c2 = *(const float2*)(y1p + col);
            acc[nt * 4 + 0] = a.x;  acc[nt * 4 + 1] = a.y;
            acc[nt * 4 + 2] = c2.x; acc[nt * 4 + 3] = c2.y;
        }

#pragma unroll
        for (int c = 0; c < 4; c++) {          // k chunks 4-7 (agg half)
            int kb = c * 16;
            float2 f00 = *(const float2*)(ar0 + kb + 2 * t4);
            float2 f01 = *(const float2*)(ar0 + kb + 8 + 2 * t4);
            float2 f10 = *(const float2*)(ar1 + kb + 2 * t4);
            float2 f11 = *(const float2*)(ar1 + kb + 8 + 2 * t4);

            uint32_t ah0, al0, ah1, al1, ah2, al2, ah3, al3;
            split2_bf16(f00.x, f00.y, ah0, al0);
            split2_bf16(f10.x, f10.y, ah1, al1);
            split2_bf16(f01.x, f01.y, ah2, al2);
            split2_bf16(f11.x, f11.y, ah3, al3);

#pragma unroll
            for (int nt = 0; nt < 8; nt++) {
                int off = (nt * 8 + g) * W1S + c * 4 + t4;
                uint2 bh = whi[off];
                uint2 bl = wlo[off];
                float* cc = acc + nt * 4;
                mma_bf16(cc, ah0, ah1, ah2, ah3, bh.x, bh.y);
                mma_bf16(cc, ah0, ah1, ah2, ah3, bl.x, bl.y);
                mma_bf16(cc, al0, al1, al2, al3, bh.x, bh.y);
            }
        }

        // ---- epilogue: bias + ReLU + LayerNorm + store ----
        float v0[16], v1[16];
        float s0 = 0.0f, s1 = 0.0f;
#pragma unroll
        for (int nt = 0; nt < 8; nt++) {
            int col = nt * 8 + 2 * t4;
            float2 bb = *(const float2*)&bias[col];
            float a = fmaxf(acc[nt * 4 + 0] + bb.x, 0.0f);
            float bq = fmaxf(acc[nt * 4 + 1] + bb.y, 0.0f);
            float cq = fmaxf(acc[nt * 4 + 2] + bb.x, 0.0f);
            float dq = fmaxf(acc[nt * 4 + 3] + bb.y, 0.0f);
            v0[nt * 2] = a;  v0[nt * 2 + 1] = bq;
            v1[nt * 2] = cq; v1[nt * 2 + 1] = dq;
            s0 += a + bq;
            s1 += cq + dq;
        }
        s0 += __shfl_xor_sync(0xffffffffu, s0, 1);
        s0 += __shfl_xor_sync(0xffffffffu, s0, 2);
        s1 += __shfl_xor_sync(0xffffffffu, s1, 1);
        s1 += __shfl_xor_sync(0xffffffffu, s1, 2);
        float mu0 = s0 * (1.0f / D), mu1 = s1 * (1.0f / D);

        float ss0 = 0.0f, ss1 = 0.0f;
#pragma unroll
        for (int i = 0; i < 16; i++) {
            float d0 = v0[i] - mu0; ss0 += d0 * d0;
            float d1 = v1[i] - mu1; ss1 += d1 * d1;
        }
        ss0 += __shfl_xor_sync(0xffffffffu, ss0, 1);
        ss0 += __shfl_xor_sync(0xffffffffu, ss0, 2);
        ss1 += __shfl_xor_sync(0xffffffffu, ss1, 1);
        ss1 += __shfl_xor_sync(0xffffffffu, ss1, 2);
        float rs0 = rsqrtf(ss0 * (1.0f / D) + 1e-5f);
        float rs1 = rsqrtf(ss1 * (1.0f / D) + 1e-5f);

        float* o0 = out + (size_t)node0 * D;
        float* o1 = out + (size_t)(node0 + 8) * D;
#pragma unroll
        for (int nt = 0; nt < 8; nt++) {
            int col = nt * 8 + 2 * t4;
            float2 gg = *(const float2*)&gam[col];
            float2 be = *(const float2*)&bet[col];
            float2 w0, w1;
            w0.x = (v0[nt * 2]     - mu0) * rs0 * gg.x + be.x;
            w0.y = (v0[nt * 2 + 1] - mu0) * rs0 * gg.y + be.y;
            w1.x = (v1[nt * 2]     - mu1) * rs1 * gg.x + be.x;
            w1.y = (v1[nt * 2 + 1] - mu1) * rs1 * gg.y + be.y;
            *(float2*)(o0 + col) = w0;
            *(float2*)(o1 + col) = w1;
        }
    }
}

// ---------------------------------------------------------------------------
extern "C" void kernel_launch(void* const* d_in, const int* in_sizes, int n_in,
                              void* d_out, int out_size) {
    const float* x     = (const float*)d_in[0];
    const int*   ei    = (const int*)d_in[1];
    const float* W     = (const float*)d_in[2];
    const float* b     = (const float*)d_in[3];
    const float* gamma = (const float*)d_in[4];
    const float* beta  = (const float*)d_in[5];
    float*       out   = (float*)d_out;

    (void)in_sizes; (void)n_in; (void)out_size;

    cudaFuncSetAttribute(fill_y1_kernel,
                         cudaFuncAttributeMaxDynamicSharedMemorySize,
                         SM2_TOTAL * (int)sizeof(uint32_t));
    cudaFuncSetAttribute(finalize2_kernel,
                         cudaFuncAttributeMaxDynamicSharedMemorySize,
                         SMF_TOTAL * (int)sizeof(uint32_t));

    setup_kernel<<<(NN + 255) / 256, 256>>>(W);

    int fill_blocks = (EE / 2 + 255) / 256;      // 3125
    fill_y1_kernel<<<FGRID + fill_blocks, 256,
                     SM2_TOTAL * sizeof(uint32_t)>>>(x, ei);

    aggregate_kernel<<<(NN / 2 * 32 + 255) / 256, 256>>>(x);

    finalize2_kernel<<<FGRID, 256,
                       SMF_TOTAL * sizeof(uint32_t)>>>(b, gamma, beta, out);
}